// round 15
// baseline (speedup 1.0000x reference)
#include <cuda_runtime.h>
#include <cuda_fp16.h>
#include <cstdint>

// out = LeakyReLU( D^-1 * (A @ (X @ W^T)) + b ),  B=32, N=1024, F=128
//
// wconv : W fp32 -> g_wh fp16 [o][f] (once).
// k_xw  : XW = X @ W^T fp16 mma (R12, proven). Output fp16 [m][o].
// k_main: C = A @ XW fp16 mma. A: LDG fp32 -> cvt -> STS fp16 (2-buffer),
//         frags via non-trans ldmatrix; deg = exact fp32 rowsum in producer.
//         B: 3-deep cp.async ring + ldmatrix.trans, issued AFTER the sync
//         (single barrier per stage, race-free ordering).

#define NEG_SLOPE 0.01f

__device__ __half g_xw[32u * 1024u * 128u];  // fp16 XW [m][o] (8 MB)
__device__ __half g_wh[128 * 128];           // fp16 W [o][f]

// ---------------- helpers ----------------
__device__ __forceinline__ uint32_t su32(const void* p) {
    uint32_t r;
    asm("{\n\t.reg .u64 t;\n\tcvta.to.shared.u64 t, %1;\n\tcvt.u32.u64 %0, t;\n\t}"
        : "=r"(r) : "l"(p));
    return r;
}
__device__ __forceinline__ void cp16(uint32_t dst, const void* src) {
    asm volatile("cp.async.cg.shared.global [%0], [%1], 16;" :: "r"(dst), "l"(src));
}
__device__ __forceinline__ void cp_commit() {
    asm volatile("cp.async.commit_group;" ::: "memory");
}
template <int N>
__device__ __forceinline__ void cp_wait() {
    asm volatile("cp.async.wait_group %0;" :: "n"(N) : "memory");
}
__device__ __forceinline__ void mma_f16(float* c, const uint32_t* a, const uint32_t* b) {
    asm volatile(
        "mma.sync.aligned.m16n8k16.row.col.f32.f16.f16.f32 "
        "{%0,%1,%2,%3}, {%4,%5,%6,%7}, {%8,%9}, {%0,%1,%2,%3};"
        : "+f"(c[0]), "+f"(c[1]), "+f"(c[2]), "+f"(c[3])
        : "r"(a[0]), "r"(a[1]), "r"(a[2]), "r"(a[3]), "r"(b[0]), "r"(b[1]));
}
__device__ __forceinline__ void ldmat4t(uint32_t* r, uint32_t addr) {
    asm volatile(
        "ldmatrix.sync.aligned.m8n8.x4.trans.shared.b16 {%0,%1,%2,%3}, [%4];"
        : "=r"(r[0]), "=r"(r[1]), "=r"(r[2]), "=r"(r[3]) : "r"(addr));
}
__device__ __forceinline__ void ldmat4(uint32_t* r, uint32_t addr) {
    asm volatile(
        "ldmatrix.sync.aligned.m8n8.x4.shared.b16 {%0,%1,%2,%3}, [%4];"
        : "=r"(r[0]), "=r"(r[1]), "=r"(r[2]), "=r"(r[3]) : "r"(addr));
}
__device__ __forceinline__ uint32_t pack_h2(float lo, float hi) {
    uint32_t r;
    asm("cvt.rn.f16x2.f32 %0, %2, %1;" : "=r"(r) : "f"(lo), "f"(hi));
    return r;
}
__device__ __forceinline__ float leaky(float v) {
    return (v >= 0.0f) ? v : NEG_SLOPE * v;
}

// =====================================================================
// wconv: W fp32 [128][128] -> g_wh fp16. grid 16 x 256 threads. (R12)
// =====================================================================
__global__ void wconv(const float* __restrict__ W) {
    int idx = blockIdx.x * 256 + threadIdx.x;
    float4 w = ((const float4*)W)[idx];
    uint2 v;
    v.x = pack_h2(w.x, w.y);
    v.y = pack_h2(w.z, w.w);
    ((uint2*)g_wh)[idx] = v;
}

// =====================================================================
// k_xw (R12, proven): XW = X @ W^T. grid=512 (m-tiles 64), 256 thr.
// smem: Wh fp16 [128][136] (34816B, cp.async from g_wh) | Xs fp32 [64][136].
// =====================================================================
#define XW_SMEM (34816 + 34816)

__global__ __launch_bounds__(256) void k_xw(const float* __restrict__ X) {
    extern __shared__ char smx[];
    const uint32_t wh_a = su32(smx), xs_a = su32(smx + 34816);
    const float2* Xs2 = (const float2*)(smx + 34816);

    const int tid = threadIdx.x, lane = tid & 31, wid = tid >> 5;
    const int g = lane >> 2, tig = lane & 3;
    const int wr = wid & 3, wc = wid >> 2;
    const int m0 = blockIdx.x * 64;

#pragma unroll
    for (int i = 0; i < 8; i++) {
        int ch = tid + i * 256;
        int r = ch >> 4, c = ch & 15;
        cp16(wh_a + (uint32_t)(r * 272 + c * 16), (const char*)g_wh + r * 256 + c * 16);
    }
#pragma unroll
    for (int i = 0; i < 8; i++) {
        int ch = tid + i * 256;
        int r = ch >> 5, c = ch & 31;
        cp16(xs_a + (uint32_t)(r * 544 + c * 16),
             X + (size_t)(m0 + r) * 128 + c * 4);
    }
    cp_commit();
    cp_wait<0>();
    __syncthreads();

    float acc[8][4];
#pragma unroll
    for (int ni = 0; ni < 8; ni++)
#pragma unroll
        for (int q = 0; q < 4; q++) acc[ni][q] = 0.0f;

    const int n_row = (lane & 7) + ((lane >> 4) & 1) * 8;
    const int k_off = ((lane >> 3) & 1) * 8;

#pragma unroll
    for (int s = 0; s < 8; s++) {
        int base = (wr * 16 + g) * 68 + s * 8 + tig;
        float2 u0 = Xs2[base];
        float2 u1 = Xs2[base + 8 * 68];
        float2 u2 = Xs2[base + 4];
        float2 u3 = Xs2[base + 8 * 68 + 4];
        uint32_t a[4] = {pack_h2(u0.x, u0.y), pack_h2(u1.x, u1.y),
                         pack_h2(u2.x, u2.y), pack_h2(u3.x, u3.y)};
#pragma unroll
        for (int j = 0; j < 4; j++) {
            int nr = wc * 64 + j * 16 + n_row;
            uint32_t addr = wh_a + (uint32_t)(nr * 136 + s * 16 + k_off) * 2;
            uint32_t bfr[4];
            ldmat4(bfr, addr);
            mma_f16(acc[j * 2 + 0], a, &bfr[0]);
            mma_f16(acc[j * 2 + 1], a, &bfr[2]);
        }
    }

    uint32_t* outp = (uint32_t*)g_xw;
    const int row = m0 + wr * 16 + g;
#pragma unroll
    for (int ni = 0; ni < 8; ni++) {
        int col2 = wc * 32 + ni * 4 + tig;
        outp[(size_t)row * 64 + col2] = pack_h2(acc[ni][0], acc[ni][1]);
        outp[(size_t)(row + 8) * 64 + col2] = pack_h2(acc[ni][2], acc[ni][3]);
    }
}

// =====================================================================
// k_main: per batch C = A @ XW (fp16 mma), BM=128; grid (8,32), 256 thr,
// 8 warps: wr=wid&3 (m32), wc=wid>>2 (n64).
// A: fp16 smem, 2 buffers x [128 rows][40 halves] (80B rows) = 20480B.
// B: 3 x [32][136] fp16 cp.async ring (26112B) + ldmat4t.
// Stage loop ordering (ONE sync, race-free):
//   stA(s); cp_wait(B(s) done); sync; loadB(s+2); ldA(s+1); compute(s)
// =====================================================================
#define AH2 20480
#define BS3 26112
#define MAIN_SMEM (AH2 + BS3 + 1024)

__global__ __launch_bounds__(256, 2) void k_main(const float* __restrict__ A,
                                                 const float* __restrict__ bias,
                                                 float* __restrict__ out) {
    extern __shared__ char smc[];
    float* dega = (float*)(smc + AH2 + BS3);
    float* degb = dega + 128;
    const uint32_t ah_a = su32(smc), bs_a = su32(smc + AH2);

    const int tid = threadIdx.x, lane = tid & 31, wid = tid >> 5;
    const int g = lane >> 2, tig = lane & 3;
    const int wr = wid & 3, wc = wid >> 2;
    const int m0 = blockIdx.x * 128, bz = blockIdx.y;
    const float* Ab = A + (size_t)bz * 1024 * 1024;
    const __half* Bp = g_xw + (size_t)bz * 131072;

    // producer mapping: row = tid&127, k-half = (tid>>7)*16
    const int prow = tid & 127, pkh = (tid >> 7) * 16;
    const float* abase = Ab + (size_t)(m0 + prow) * 1024 + pkh;
    const uint32_t asts = ah_a + (uint32_t)(prow * 80 + pkh * 2);

    float4 ar[4];
    float dreg = 0.0f;
    auto ldA = [&](int s) {
        const float4* p = (const float4*)(abase + s * 32);
        ar[0] = p[0]; ar[1] = p[1]; ar[2] = p[2]; ar[3] = p[3];
#pragma unroll
        for (int j = 0; j < 4; j++)
            dreg += (ar[j].x + ar[j].y) + (ar[j].z + ar[j].w);
    };
    auto stA = [&](int buf) {
        uint4 v0, v1;
        v0.x = pack_h2(ar[0].x, ar[0].y); v0.y = pack_h2(ar[0].z, ar[0].w);
        v0.z = pack_h2(ar[1].x, ar[1].y); v0.w = pack_h2(ar[1].z, ar[1].w);
        v1.x = pack_h2(ar[2].x, ar[2].y); v1.y = pack_h2(ar[2].z, ar[2].w);
        v1.z = pack_h2(ar[3].x, ar[3].y); v1.w = pack_h2(ar[3].z, ar[3].w);
        uint32_t d = asts + buf * 10240;
        asm volatile("st.shared.v4.b32 [%0], {%1,%2,%3,%4};"
                     :: "r"(d), "r"(v0.x), "r"(v0.y), "r"(v0.z), "r"(v0.w));
        asm volatile("st.shared.v4.b32 [%0], {%1,%2,%3,%4};"
                     :: "r"(d + 16), "r"(v1.x), "r"(v1.y), "r"(v1.z), "r"(v1.w));
    };

    auto loadB = [&](int buf, int s) {
        const char* src = (const char*)(Bp + s * 4096);
#pragma unroll
        for (int i = 0; i < 2; i++) {
            int gi = tid + i * 256;
            int r = gi >> 4, c = gi & 15;
            cp16(bs_a + (uint32_t)(buf * 8704 + r * 272 + c * 16),
                 src + r * 256 + c * 16);
        }
        cp_commit();
    };

    float acc[2][8][4];
#pragma unroll
    for (int mi = 0; mi < 2; mi++)
#pragma unroll
        for (int ni = 0; ni < 8; ni++)
#pragma unroll
            for (int q = 0; q < 4; q++) acc[mi][ni][q] = 0.0f;

    loadB(0, 0);
    loadB(1, 1);
    ldA(0);

    // A-frag ldmatrix address pieces (non-trans, [m][k] row-major)
    const int arow = wr * 32 + (lane & 7) + ((lane >> 3) & 1) * 8;
    const int acol = ((lane >> 4) & 1) * 16;  // bytes (k +8 halves)
    const int lm_k = lane & 15;
    const int lm_n8 = (lane >> 4) * 8;

    for (int s = 0; s < 32; s++) {
        stA(s & 1);
        if (s < 31) cp_wait<1>();  // B(s) complete (B(s+1) may be in flight)
        else cp_wait<0>();
        __syncthreads();
        // safe now: compute(s-1) is behind the barrier
        if (s + 2 < 32) loadB((s + 2) % 3, s + 2);
        if (s < 31) ldA(s + 1);

        const uint32_t abuf = ah_a + (s & 1) * 10240;
        const uint32_t bsb = bs_a + (s % 3) * 8704;
#pragma unroll
        for (int h = 0; h < 2; h++) {
            uint32_t a[2][4];
#pragma unroll
            for (int mi = 0; mi < 2; mi++)
                ldmat4(a[mi], abuf + (uint32_t)((arow + mi * 16) * 80 + h * 32 + acol));
            uint32_t bfr[4][4];
#pragma unroll
            for (int j = 0; j < 4; j++) {
                int n0 = wc * 64 + j * 16 + lm_n8;
                ldmat4t(bfr[j], bsb + (uint32_t)((h * 16 + lm_k) * 272 + n0 * 2));
            }
#pragma unroll
            for (int ni = 0; ni < 8; ni++) {
                const uint32_t* b = &bfr[ni >> 1][(ni & 1) * 2];
                mma_f16(acc[0][ni], a[0], b);
                mma_f16(acc[1][ni], a[1], b);
            }
        }
    }

    // deg: exact fp32 partials per k-half, combined in epilogue
    __syncthreads();  // all compute done before deg buffers reuse smem region
    if (tid < 128) dega[prow] = dreg;
    else degb[prow] = dreg;
    __syncthreads();

    float inv[2][2];
#pragma unroll
    for (int mi = 0; mi < 2; mi++) {
        int r0 = wr * 32 + mi * 16 + g;
        inv[mi][0] = 1.0f / (dega[r0] + degb[r0]);
        inv[mi][1] = 1.0f / (dega[r0 + 8] + degb[r0 + 8]);
    }

#pragma unroll
    for (int ni = 0; ni < 8; ni++) {
        int col = wc * 64 + ni * 8 + tig * 2;
        float2 bv = *(const float2*)(bias + col);
#pragma unroll
        for (int mi = 0; mi < 2; mi++) {
            int row = m0 + wr * 32 + mi * 16 + g;
            float2 v0, v1;
            v0.x = leaky(fmaf(acc[mi][ni][0], inv[mi][0], bv.x));
            v0.y = leaky(fmaf(acc[mi][ni][1], inv[mi][0], bv.y));
            v1.x = leaky(fmaf(acc[mi][ni][2], inv[mi][1], bv.x));
            v1.y = leaky(fmaf(acc[mi][ni][3], inv[mi][1], bv.y));
            *(float2*)(out + ((size_t)bz * 1024 + row) * 128 + col) = v0;
            *(float2*)(out + ((size_t)bz * 1024 + row + 8) * 128 + col) = v1;
        }
    }
}

// ---------------- host ----------------
extern "C" void kernel_launch(void* const* d_in, const int* in_sizes, int n_in,
                              void* d_out, int out_size) {
    const float* X    = (const float*)d_in[0];  // [32,1024,128]
    const float* adj  = (const float*)d_in[1];  // [32,1024,1024]
    const float* W    = (const float*)d_in[2];  // [128,128]
    const float* bias = (const float*)d_in[3];  // [128]
    float* out = (float*)d_out;                 // [32,1024,128]

    static int inited = 0;
    if (!inited) {
        cudaFuncSetAttribute(k_xw, cudaFuncAttributeMaxDynamicSharedMemorySize, XW_SMEM);
        cudaFuncSetAttribute(k_main, cudaFuncAttributeMaxDynamicSharedMemorySize, MAIN_SMEM);
        inited = 1;
    }

    wconv<<<16, 256>>>(W);
    k_xw<<<512, 256, XW_SMEM>>>(X);
    k_main<<<dim3(8, 32), 256, MAIN_SMEM>>>(adj, bias, out);
}

// round 16
// speedup vs baseline: 1.4281x; 1.4281x over previous
#include <cuda_runtime.h>
#include <cuda_fp16.h>
#include <cstdint>

// out = LeakyReLU( D^-1 * (A @ (X @ W^T)) + b ),  B=32, N=1024, F=128
//
// wconv : W fp32 -> g_wh fp16 [o][f] (once).
// k_xw  : XW = X @ W^T fp16 mma (R12, proven). Output fp16 [m][o].
// k_main: C = A @ XW fp16 mma, BM=128, BK=64, 2-stage cp.async pipeline
//         (R9/R12 structure, half the stages/barriers). deg = rowsum(A)
//         FADD on fp32 values; epilogue leaky(C/deg + b).

#define NEG_SLOPE 0.01f

__device__ __half g_xw[32u * 1024u * 128u];  // fp16 XW [m][o] (8 MB)
__device__ __half g_wh[128 * 128];           // fp16 W [o][f]

// ---------------- helpers ----------------
__device__ __forceinline__ uint32_t su32(const void* p) {
    uint32_t r;
    asm("{\n\t.reg .u64 t;\n\tcvta.to.shared.u64 t, %1;\n\tcvt.u32.u64 %0, t;\n\t}"
        : "=r"(r) : "l"(p));
    return r;
}
__device__ __forceinline__ void cp16(uint32_t dst, const void* src) {
    asm volatile("cp.async.cg.shared.global [%0], [%1], 16;" :: "r"(dst), "l"(src));
}
__device__ __forceinline__ void cp_commit() {
    asm volatile("cp.async.commit_group;" ::: "memory");
}
template <int N>
__device__ __forceinline__ void cp_wait() {
    asm volatile("cp.async.wait_group %0;" :: "n"(N) : "memory");
}
__device__ __forceinline__ void mma_f16(float* c, const uint32_t* a, const uint32_t* b) {
    asm volatile(
        "mma.sync.aligned.m16n8k16.row.col.f32.f16.f16.f32 "
        "{%0,%1,%2,%3}, {%4,%5,%6,%7}, {%8,%9}, {%0,%1,%2,%3};"
        : "+f"(c[0]), "+f"(c[1]), "+f"(c[2]), "+f"(c[3])
        : "r"(a[0]), "r"(a[1]), "r"(a[2]), "r"(a[3]), "r"(b[0]), "r"(b[1]));
}
__device__ __forceinline__ void ldmat4t(uint32_t* r, uint32_t addr) {
    asm volatile(
        "ldmatrix.sync.aligned.m8n8.x4.trans.shared.b16 {%0,%1,%2,%3}, [%4];"
        : "=r"(r[0]), "=r"(r[1]), "=r"(r[2]), "=r"(r[3]) : "r"(addr));
}
__device__ __forceinline__ void ldmat4(uint32_t* r, uint32_t addr) {
    asm volatile(
        "ldmatrix.sync.aligned.m8n8.x4.shared.b16 {%0,%1,%2,%3}, [%4];"
        : "=r"(r[0]), "=r"(r[1]), "=r"(r[2]), "=r"(r[3]) : "r"(addr));
}
__device__ __forceinline__ uint32_t pack_h2(float lo, float hi) {
    uint32_t r;
    asm("cvt.rn.f16x2.f32 %0, %2, %1;" : "=r"(r) : "f"(lo), "f"(hi));
    return r;
}
__device__ __forceinline__ float leaky(float v) {
    return (v >= 0.0f) ? v : NEG_SLOPE * v;
}

// =====================================================================
// wconv: W fp32 [128][128] -> g_wh fp16. grid 16 x 256 threads. (R12)
// =====================================================================
__global__ void wconv(const float* __restrict__ W) {
    int idx = blockIdx.x * 256 + threadIdx.x;
    float4 w = ((const float4*)W)[idx];
    uint2 v;
    v.x = pack_h2(w.x, w.y);
    v.y = pack_h2(w.z, w.w);
    ((uint2*)g_wh)[idx] = v;
}

// =====================================================================
// k_xw (R12, proven): XW = X @ W^T. grid=512 (m-tiles 64), 256 thr.
// smem: Wh fp16 [128][136] (34816B, cp.async from g_wh) | Xs fp32 [64][136].
// =====================================================================
#define XW_SMEM (34816 + 34816)

__global__ __launch_bounds__(256) void k_xw(const float* __restrict__ X) {
    extern __shared__ char smx[];
    const uint32_t wh_a = su32(smx), xs_a = su32(smx + 34816);
    const float2* Xs2 = (const float2*)(smx + 34816);

    const int tid = threadIdx.x, lane = tid & 31, wid = tid >> 5;
    const int g = lane >> 2, tig = lane & 3;
    const int wr = wid & 3, wc = wid >> 2;
    const int m0 = blockIdx.x * 64;

#pragma unroll
    for (int i = 0; i < 8; i++) {
        int ch = tid + i * 256;
        int r = ch >> 4, c = ch & 15;
        cp16(wh_a + (uint32_t)(r * 272 + c * 16), (const char*)g_wh + r * 256 + c * 16);
    }
#pragma unroll
    for (int i = 0; i < 8; i++) {
        int ch = tid + i * 256;
        int r = ch >> 5, c = ch & 31;
        cp16(xs_a + (uint32_t)(r * 544 + c * 16),
             X + (size_t)(m0 + r) * 128 + c * 4);
    }
    cp_commit();
    cp_wait<0>();
    __syncthreads();

    float acc[8][4];
#pragma unroll
    for (int ni = 0; ni < 8; ni++)
#pragma unroll
        for (int q = 0; q < 4; q++) acc[ni][q] = 0.0f;

    const int n_row = (lane & 7) + ((lane >> 4) & 1) * 8;
    const int k_off = ((lane >> 3) & 1) * 8;

#pragma unroll
    for (int s = 0; s < 8; s++) {
        int base = (wr * 16 + g) * 68 + s * 8 + tig;
        float2 u0 = Xs2[base];
        float2 u1 = Xs2[base + 8 * 68];
        float2 u2 = Xs2[base + 4];
        float2 u3 = Xs2[base + 8 * 68 + 4];
        uint32_t a[4] = {pack_h2(u0.x, u0.y), pack_h2(u1.x, u1.y),
                         pack_h2(u2.x, u2.y), pack_h2(u3.x, u3.y)};
#pragma unroll
        for (int j = 0; j < 4; j++) {
            int nr = wc * 64 + j * 16 + n_row;
            uint32_t addr = wh_a + (uint32_t)(nr * 136 + s * 16 + k_off) * 2;
            uint32_t bfr[4];
            ldmat4(bfr, addr);
            mma_f16(acc[j * 2 + 0], a, &bfr[0]);
            mma_f16(acc[j * 2 + 1], a, &bfr[2]);
        }
    }

    uint32_t* outp = (uint32_t*)g_xw;
    const int row = m0 + wr * 16 + g;
#pragma unroll
    for (int ni = 0; ni < 8; ni++) {
        int col2 = wc * 32 + ni * 4 + tig;
        outp[(size_t)row * 64 + col2] = pack_h2(acc[ni][0], acc[ni][1]);
        outp[(size_t)(row + 8) * 64 + col2] = pack_h2(acc[ni][2], acc[ni][3]);
    }
}

// =====================================================================
// k_main: per batch C = A @ XW (fp16 mma), BM=128, BK=64; grid (8,32),
// 256 thr, 8 warps: wr=wid&3 (m32), wc=wid>>2 (n64). 2-stage pipeline.
// smem: As 2 x [128][72] fp32 (73728B) | Bs 2 x [64][136] fp16 (34816B)
// =====================================================================
#define AP2 72     // A row pad (floats); frag LDS stride 36 float2 (CF)
#define AS2B 73728
#define BS2B 34816
#define MAIN_SMEM (AS2B + BS2B + 512)

__global__ __launch_bounds__(256, 2) void k_main(const float* __restrict__ A,
                                                 const float* __restrict__ bias,
                                                 float* __restrict__ out) {
    extern __shared__ float sm[];
    char* smc = (char*)sm;
    const float2* As2 = (const float2*)sm;
    float* degs = (float*)(smc + AS2B + BS2B);
    const uint32_t as_a = su32(sm), bs_a = su32(smc + AS2B);

    const int tid = threadIdx.x, lane = tid & 31, wid = tid >> 5;
    const int g = lane >> 2, tig = lane & 3;
    const int wr = wid & 3, wc = wid >> 2;
    const int m0 = blockIdx.x * 128, bz = blockIdx.y;
    const float* Ab = A + (size_t)bz * 1024 * 1024;
    const __half* Bp = g_xw + (size_t)bz * 131072;

    auto loadT = [&](int buf, int s) {
        // A: 128 rows x 16 float4 (64 k-cols) = 2048 chunks, 8/thread
#pragma unroll
        for (int i = 0; i < 8; i++) {
            int gi = tid + i * 256;
            int r = gi >> 4, c = gi & 15;
            cp16(as_a + (uint32_t)(((buf * 128 + r) * AP2 + c * 4) * 4),
                 Ab + (size_t)(m0 + r) * 1024 + s * 64 + c * 4);
        }
        // B: 64 rows x 16 chunks at 272B stride = 1024 chunks, 4/thread
        const char* src = (const char*)(Bp + s * 8192);
#pragma unroll
        for (int i = 0; i < 4; i++) {
            int gi = tid + i * 256;
            int r = gi >> 4, c = gi & 15;
            cp16(bs_a + (uint32_t)(buf * 17408 + r * 272 + c * 16),
                 src + r * 256 + c * 16);
        }
        cp_commit();
    };

    float acc[2][8][4];
#pragma unroll
    for (int mi = 0; mi < 2; mi++)
#pragma unroll
        for (int ni = 0; ni < 8; ni++)
#pragma unroll
            for (int q = 0; q < 4; q++) acc[mi][ni][q] = 0.0f;
    float dg[2][2] = {{0.0f, 0.0f}, {0.0f, 0.0f}};

    loadT(0, 0);

    const int lm_k = lane & 15;
    const int lm_n8 = (lane >> 4) * 8;

    for (int s = 0; s < 16; s++) {
        if (s < 15) { loadT((s + 1) & 1, s + 1); cp_wait<1>(); }
        else cp_wait<0>();
        __syncthreads();
        const int buf = s & 1;
        const uint32_t bsb = bs_a + buf * 17408;

#pragma unroll
        for (int h = 0; h < 4; h++) {  // four k16 halves of the k64 stage
            uint32_t a[2][4];
#pragma unroll
            for (int mi = 0; mi < 2; mi++) {
                int row = wr * 32 + mi * 16 + g;
                int base = (buf * 128 + row) * (AP2 / 2) + h * 8 + tig;
                float2 u0 = As2[base];
                float2 u1 = As2[base + 8 * (AP2 / 2)];
                float2 u2 = As2[base + 4];
                float2 u3 = As2[base + 8 * (AP2 / 2) + 4];
                a[mi][0] = pack_h2(u0.x, u0.y);
                a[mi][1] = pack_h2(u1.x, u1.y);
                a[mi][2] = pack_h2(u2.x, u2.y);
                a[mi][3] = pack_h2(u3.x, u3.y);
                if (wc == 0) {
                    dg[mi][0] += (u0.x + u0.y) + (u2.x + u2.y);
                    dg[mi][1] += (u1.x + u1.y) + (u3.x + u3.y);
                }
            }
            uint32_t bfr[4][4];
#pragma unroll
            for (int j = 0; j < 4; j++) {
                int n0 = wc * 64 + j * 16 + lm_n8;
                ldmat4t(bfr[j], bsb + (uint32_t)((h * 16 + lm_k) * 272 + n0 * 2));
            }
#pragma unroll
            for (int ni = 0; ni < 8; ni++) {
                const uint32_t* b = &bfr[ni >> 1][(ni & 1) * 2];
                mma_f16(acc[0][ni], a[0], b);
                mma_f16(acc[1][ni], a[1], b);
            }
        }
        __syncthreads();
    }

    if (wc == 0) {
#pragma unroll
        for (int mi = 0; mi < 2; mi++)
#pragma unroll
            for (int r = 0; r < 2; r++) {
                float v = dg[mi][r];
                v += __shfl_xor_sync(0xffffffffu, v, 1);
                v += __shfl_xor_sync(0xffffffffu, v, 2);
                if (tig == 0) degs[wr * 32 + mi * 16 + r * 8 + g] = v;
            }
    }
    __syncthreads();

    float inv[2][2];
#pragma unroll
    for (int mi = 0; mi < 2; mi++) {
        inv[mi][0] = 1.0f / degs[wr * 32 + mi * 16 + g];
        inv[mi][1] = 1.0f / degs[wr * 32 + mi * 16 + g + 8];
    }

#pragma unroll
    for (int ni = 0; ni < 8; ni++) {
        int col = wc * 64 + ni * 8 + tig * 2;
        float2 bv = *(const float2*)(bias + col);
#pragma unroll
        for (int mi = 0; mi < 2; mi++) {
            int row = m0 + wr * 32 + mi * 16 + g;
            float2 v0, v1;
            v0.x = leaky(fmaf(acc[mi][ni][0], inv[mi][0], bv.x));
            v0.y = leaky(fmaf(acc[mi][ni][1], inv[mi][0], bv.y));
            v1.x = leaky(fmaf(acc[mi][ni][2], inv[mi][1], bv.x));
            v1.y = leaky(fmaf(acc[mi][ni][3], inv[mi][1], bv.y));
            *(float2*)(out + ((size_t)bz * 1024 + row) * 128 + col) = v0;
            *(float2*)(out + ((size_t)bz * 1024 + row + 8) * 128 + col) = v1;
        }
    }
}

// ---------------- host ----------------
extern "C" void kernel_launch(void* const* d_in, const int* in_sizes, int n_in,
                              void* d_out, int out_size) {
    const float* X    = (const float*)d_in[0];  // [32,1024,128]
    const float* adj  = (const float*)d_in[1];  // [32,1024,1024]
    const float* W    = (const float*)d_in[2];  // [128,128]
    const float* bias = (const float*)d_in[3];  // [128]
    float* out = (float*)d_out;                 // [32,1024,128]

    static int inited = 0;
    if (!inited) {
        cudaFuncSetAttribute(k_xw, cudaFuncAttributeMaxDynamicSharedMemorySize, XW_SMEM);
        cudaFuncSetAttribute(k_main, cudaFuncAttributeMaxDynamicSharedMemorySize, MAIN_SMEM);
        inited = 1;
    }

    wconv<<<16, 256>>>(W);
    k_xw<<<512, 256, XW_SMEM>>>(X);
    k_main<<<dim3(8, 32), 256, MAIN_SMEM>>>(adj, bias, out);
}